// round 10
// baseline (speedup 1.0000x reference)
#include <cuda_runtime.h>
#include <math.h>

#define HH 128
#define WW 128
#define NPIX (HH * WW)
#define NPTS 16384
#define KNN 16
#define FDIM 64
#define CAP 12
#define OVFCAP 512
#define FULLMASK 0xffffffffu

#define OFF_DEPTH 0
#define OFF_COLOR (NPIX)
#define OFF_FEAT  (NPIX + NPIX * 3)
#define OFF_MASK  (NPIX + NPIX * 3 + NPIX * FDIM)

// ---- device scratch ----
__device__ int    g_cnt[NPIX + 1];
__device__ float4 g_bucket[NPIX * CAP];
__device__ float4 g_ovf[OVFCAP];

__global__ void __launch_bounds__(256) project_bin_kernel(
    const float* __restrict__ pts, const float* __restrict__ intr) {
    int i = blockIdx.x * 256 + threadIdx.x;
    if (i >= NPTS) return;
    float x = __ldg(&pts[3 * i + 0]);
    float y = __ldg(&pts[3 * i + 1]);
    float z = __ldg(&pts[3 * i + 2]);
    float fx = intr[0], cx = intr[2], fy = intr[4], cy = intr[5];
    bool valid = z > 1e-6f;
    float sz = valid ? z : 1.0f;
    float u = __fadd_rn(__fdiv_rn(__fmul_rn(x, fx), sz), cx);
    float v = __fadd_rn(__fdiv_rn(__fmul_rn(y, fy), sz), cy);
    if (!valid) { u = 1e9f; v = 1e9f; }
    if (u > -2.0f && u < 130.0f && v > -2.0f && v < 130.0f) {
        int cu = min(max((int)floorf(u), 0), WW - 1);
        int cv = min(max((int)floorf(v), 0), HH - 1);
        int cell = cv * WW + cu;
        float4 rec = make_float4(u, v, z, __int_as_float(i));
        int pos = atomicAdd(&g_cnt[cell], 1);
        if (pos < CAP) {
            g_bucket[cell * CAP + pos] = rec;
        } else {
            int o = atomicAdd(&g_cnt[NPIX], 1);
            if (o < OVFCAP) g_ovf[o] = rec;
        }
    }
}

// warp per pixel: 16384 warps, 2048 blocks x 256
__global__ void __launch_bounds__(256) knn_feat_kernel(
    const float* __restrict__ colors, const float* __restrict__ feats,
    float* __restrict__ out) {
    __shared__ float2 s_c[8][KNN];               // compacted {wn, bitcast(id)}
    __shared__ unsigned short s_map[8][64];      // candidate j -> (cellLane<<8)|slot
    __shared__ int    s_fn[8];

    int lane = threadIdx.x & 31;
    int warp = threadIdx.x >> 5;
    int p = blockIdx.x * 8 + warp;
    int pi = p >> 7, pj = p & 127;
    float px = pj + 0.5f, py = pi + 0.5f;

    // lane -> neighbor cell (5x5)
    int rr = lane / 5, qq = lane - 5 * rr;
    int cv = pi - 2 + rr, cu = pj - 2 + qq;
    bool cok = (lane < 25) && (cv >= 0) && (cv < HH) && (cu >= 0) && (cu < WW);
    int cell = cok ? (cv * WW + cu) : 0;
    int cnt = cok ? min(g_cnt[cell], CAP) : 0;

    // warp inclusive scan of counts
    int incl = cnt;
#pragma unroll
    for (int o = 1; o < 32; o <<= 1) {
        int v = __shfl_up_sync(FULLMASK, incl, o);
        if (lane >= o) incl += v;
    }
    int T = __shfl_sync(FULLMASK, incl, 31);
    int excl = incl - cnt;
    int novf = g_cnt[NPIX];

    bool fastpath = (T <= 64) && (novf == 0);
    unsigned lmask = (1u << lane) - 1u;

    float dsum = 0.0f, c0s = 0.0f, c1s = 0.0f, c2s = 0.0f;
    int anyok = 0;

    if (fastpath) {
        // build packed inverse map (avg 1 store per lane)
        for (int i = 0; i < cnt; ++i)
            s_map[warp][excl + i] = (unsigned short)((lane << 8) | i);
        __syncwarp();

        float d2_0 = 4.0f, d2_1 = 4.0f, z0 = 0.0f, z1 = 0.0f;
        int id0 = 0, id1 = 0;
        bool act0 = false, act1 = false;

        // batch 0: candidate j = lane
        {
            int mv = (lane < T) ? (int)s_map[warp][lane] : 0;
            int cl = __shfl_sync(FULLMASK, cell, mv >> 8);   // convergent
            if (lane < T) {
                float4 rec = g_bucket[cl * CAP + (mv & 255)];
                float du = __fsub_rn(px, rec.x);
                float dv = __fsub_rn(py, rec.y);
                float d2 = __fadd_rn(__fmul_rn(du, du), __fmul_rn(dv, dv));
                if (d2 < 4.0f) { act0 = true; d2_0 = d2; z0 = rec.z; id0 = __float_as_int(rec.w); }
            }
        }
        // batch 1: candidate j = lane + 32 (uniform guard)
        if (T > 32) {
            int j = lane + 32;
            int mv = (j < T) ? (int)s_map[warp][j] : 0;
            int cl = __shfl_sync(FULLMASK, cell, mv >> 8);
            if (j < T) {
                float4 rec = g_bucket[cl * CAP + (mv & 255)];
                float du = __fsub_rn(px, rec.x);
                float dv = __fsub_rn(py, rec.y);
                float d2 = __fadd_rn(__fmul_rn(du, du), __fmul_rn(dv, dv));
                if (d2 < 4.0f) { act1 = true; d2_1 = d2; z1 = rec.z; id1 = __float_as_int(rec.w); }
            }
        }

        // exact top-16 eviction (rare)
        int m = __popc(__ballot_sync(FULLMASK, act0)) + __popc(__ballot_sync(FULLMASK, act1));
        while (m > KNN) {
            float lm = -1.0f;
            if (act0) lm = d2_0;
            if (act1 && d2_1 > lm) lm = d2_1;
            float gm = lm;
#pragma unroll
            for (int o = 16; o; o >>= 1)
                gm = fmaxf(gm, __shfl_xor_sync(FULLMASK, gm, o));
            unsigned v1 = __ballot_sync(FULLMASK, act1 && d2_1 == gm);
            unsigned v0 = __ballot_sync(FULLMASK, act0 && d2_0 == gm);
            if (v1) { if (lane == 31 - __clz(v1)) act1 = false; }
            else    { if (lane == 31 - __clz(v0)) act0 = false; }
            --m;
        }

        // weights + blend reductions
        float w0 = act0 ? __expf(-d2_0) : 0.0f;
        float w1 = act1 ? __expf(-d2_1) : 0.0f;
        float ws = w0 + w1;
        float wz = w0 * z0 + w1 * z1;
        float wc0 = 0.0f, wc1 = 0.0f, wc2 = 0.0f;
        if (act0) {
            wc0 = w0 * __ldg(&colors[3 * id0 + 0]);
            wc1 = w0 * __ldg(&colors[3 * id0 + 1]);
            wc2 = w0 * __ldg(&colors[3 * id0 + 2]);
        }
        if (act1) {
            wc0 += w1 * __ldg(&colors[3 * id1 + 0]);
            wc1 += w1 * __ldg(&colors[3 * id1 + 1]);
            wc2 += w1 * __ldg(&colors[3 * id1 + 2]);
        }
#pragma unroll
        for (int o = 16; o; o >>= 1) {
            ws  += __shfl_xor_sync(FULLMASK, ws, o);
            wz  += __shfl_xor_sync(FULLMASK, wz, o);
            wc0 += __shfl_xor_sync(FULLMASK, wc0, o);
            wc1 += __shfl_xor_sync(FULLMASK, wc1, o);
            wc2 += __shfl_xor_sync(FULLMASK, wc2, o);
        }
        float winv = 1.0f / (ws + 1e-10f);
        dsum = wz * winv;
        c0s = wc0 * winv; c1s = wc1 * winv; c2s = wc2 * winv;

        // compact contributing candidates into smem: {wn, id}
        unsigned ball0 = __ballot_sync(FULLMASK, act0);
        unsigned ball1 = __ballot_sync(FULLMASK, act1);
        int n0 = __popc(ball0);
        if (act0) s_c[warp][__popc(ball0 & lmask)] = make_float2(w0 * winv, __int_as_float(id0));
        if (act1) s_c[warp][n0 + __popc(ball1 & lmask)] = make_float2(w1 * winv, __int_as_float(id1));
        if (lane == 0) s_fn[warp] = n0 + __popc(ball1);
        anyok = (ball0 | ball1) ? 1 : 0;
    } else {
        // exact scalar fallback (lane 0); warp-uniform path condition
        if (lane == 0) {
            float d2s[KNN], zs[KNN];
            int ids[KNN];
            int n = 0;
            float curmax = -1.0f;
            int argmax = 0;
            int cv0 = max(pi - 2, 0), cv1 = min(pi + 2, HH - 1);
            int cu0 = max(pj - 2, 0), cu1 = min(pj + 2, WW - 1);
            int no = min(novf, OVFCAP);
            for (int a = cv0; a <= cv1 + 1; ++a) {
                bool op = (a == cv1 + 1);
                int blo = op ? 0 : cu0, bhi = op ? 0 : cu1;
                for (int b = blo; b <= bhi; ++b) {
                    int cc;
                    const float4* bk;
                    if (op) { cc = no; bk = g_ovf; }
                    else { int ce = a * WW + b; cc = min(g_cnt[ce], CAP); bk = &g_bucket[ce * CAP]; }
                    for (int s = 0; s < cc; ++s) {
                        float4 rec = bk[s];
                        float du = __fsub_rn(px, rec.x);
                        float dv = __fsub_rn(py, rec.y);
                        float d2 = __fadd_rn(__fmul_rn(du, du), __fmul_rn(dv, dv));
                        if (d2 >= 4.0f) continue;
                        if (n < KNN) {
                            d2s[n] = d2; zs[n] = rec.z; ids[n] = __float_as_int(rec.w);
                            if (d2 > curmax) { curmax = d2; argmax = n; }
                            ++n;
                        } else if (d2 < curmax) {
                            d2s[argmax] = d2; zs[argmax] = rec.z; ids[argmax] = __float_as_int(rec.w);
                            curmax = -1.0f;
                            for (int k = 0; k < KNN; ++k)
                                if (d2s[k] > curmax) { curmax = d2s[k]; argmax = k; }
                        }
                    }
                }
            }
            float ws = 0.0f;
            for (int k = 0; k < n; ++k) { d2s[k] = __expf(-d2s[k]); ws += d2s[k]; }
            float winv = 1.0f / (ws + 1e-10f);
            float ds = 0.0f, a0 = 0.0f, a1 = 0.0f, a2 = 0.0f;
            for (int k = 0; k < n; ++k) {
                float wn = d2s[k] * winv;
                int oi = ids[k];
                ds += zs[k] * wn;
                a0 += __ldg(&colors[3 * oi + 0]) * wn;
                a1 += __ldg(&colors[3 * oi + 1]) * wn;
                a2 += __ldg(&colors[3 * oi + 2]) * wn;
                s_c[warp][k] = make_float2(wn, __int_as_float(oi));
            }
            s_fn[warp] = n;
            out[OFF_DEPTH + p] = ds;
            out[OFF_COLOR + 3 * p + 0] = a0;
            out[OFF_COLOR + 3 * p + 1] = a1;
            out[OFF_COLOR + 3 * p + 2] = a2;
            out[OFF_MASK + p] = (n > 0) ? 1.0f : 0.0f;
        }
    }
    __syncwarp();

    // zero-pad compacted list to exactly KNN entries
    int n = s_fn[warp];
    if (lane >= n && lane < KNN)
        s_c[warp][lane] = make_float2(0.0f, __int_as_float(0));
    __syncwarp();

    // ---- split gather: half-warp h does candidates h*8..h*8+7 over ALL 64 dims ----
    const float4* feats4 = (const float4*)feats;
    int half = lane >> 4;        // 0 or 1
    int dl = lane & 15;          // float4 dim group: dims 4*dl .. 4*dl+3
    float ax = 0.0f, ay = 0.0f, az = 0.0f, aw = 0.0f;
#pragma unroll 4
    for (int k = 0; k < 8; ++k) {
        float2 c = s_c[warp][half * 8 + k];     // LDS.64 broadcast (2 addrs)
        int id = __float_as_int(c.y);
        float4 f = __ldg(&feats4[id * 16 + dl]); // LDG.128
        ax += c.x * f.x; ay += c.x * f.y; az += c.x * f.z; aw += c.x * f.w;
    }
    // combine halves
    ax += __shfl_xor_sync(FULLMASK, ax, 16);
    ay += __shfl_xor_sync(FULLMASK, ay, 16);
    az += __shfl_xor_sync(FULLMASK, az, 16);
    aw += __shfl_xor_sync(FULLMASK, aw, 16);
    if (lane < 16) {
        float4* outf4 = (float4*)(out + OFF_FEAT);
        outf4[(size_t)p * 16 + lane] = make_float4(ax, ay, az, aw);
    }

    if (fastpath && lane == 0) {
        out[OFF_DEPTH + p] = dsum;
        out[OFF_COLOR + 3 * p + 0] = c0s;
        out[OFF_COLOR + 3 * p + 1] = c1s;
        out[OFF_COLOR + 3 * p + 2] = c2s;
        out[OFF_MASK + p] = anyok ? 1.0f : 0.0f;
    }
}

extern "C" void kernel_launch(void* const* d_in, const int* in_sizes, int n_in,
                              void* d_out, int out_size) {
    const float* pts    = (const float*)d_in[0];
    const float* colors = (const float*)d_in[1];
    const float* feats  = (const float*)d_in[2];
    const float* intr   = (const float*)d_in[3];
    float* out = (float*)d_out;

    void* p_cnt = nullptr;
    cudaGetSymbolAddress(&p_cnt, g_cnt);
    cudaMemsetAsync(p_cnt, 0, sizeof(int) * (NPIX + 1), 0);

    project_bin_kernel<<<NPTS / 256, 256>>>(pts, intr);
    knn_feat_kernel<<<NPIX / 8, 256>>>(colors, feats, out);
}

// round 11
// speedup vs baseline: 1.1062x; 1.1062x over previous
#include <cuda_runtime.h>
#include <math.h>

#define HH 128
#define WW 128
#define NPIX (HH * WW)
#define NPTS 16384
#define KNN 16
#define FDIM 64
#define CAP 12
#define OVFCAP 512
#define TMAX 48
#define FULLMASK 0xffffffffu

#define OFF_DEPTH 0
#define OFF_COLOR (NPIX)
#define OFF_FEAT  (NPIX + NPIX * 3)
#define OFF_MASK  (NPIX + NPIX * 3 + NPIX * FDIM)

// ---- device scratch ----
__device__ int    g_cnt[NPIX + 1];
__device__ float4 g_bucket[NPIX * CAP];
__device__ float4 g_ovf[OVFCAP];

__global__ void __launch_bounds__(256) project_bin_kernel(
    const float* __restrict__ pts, const float* __restrict__ intr) {
    int i = blockIdx.x * 256 + threadIdx.x;
    if (i >= NPTS) return;
    float x = __ldg(&pts[3 * i + 0]);
    float y = __ldg(&pts[3 * i + 1]);
    float z = __ldg(&pts[3 * i + 2]);
    float fx = intr[0], cx = intr[2], fy = intr[4], cy = intr[5];
    bool valid = z > 1e-6f;
    float sz = valid ? z : 1.0f;
    float u = __fadd_rn(__fdiv_rn(__fmul_rn(x, fx), sz), cx);
    float v = __fadd_rn(__fdiv_rn(__fmul_rn(y, fy), sz), cy);
    if (!valid) { u = 1e9f; v = 1e9f; }
    if (u > -2.0f && u < 130.0f && v > -2.0f && v < 130.0f) {
        int cu = min(max((int)floorf(u), 0), WW - 1);
        int cv = min(max((int)floorf(v), 0), HH - 1);
        int cell = cv * WW + cu;
        float4 rec = make_float4(u, v, z, __int_as_float(i));
        int pos = atomicAdd(&g_cnt[cell], 1);
        if (pos < CAP) {
            g_bucket[cell * CAP + pos] = rec;
        } else {
            int o = atomicAdd(&g_cnt[NPIX], 1);
            if (o < OVFCAP) g_ovf[o] = rec;
        }
    }
}

// half-warp per pixel: 2 pixels/warp, 8192 warps, 1024 blocks x 256
__global__ void __launch_bounds__(256) knn_feat_kernel(
    const float* __restrict__ colors, const float* __restrict__ feats,
    float* __restrict__ out) {
    __shared__ unsigned s_map[8][2][TMAX];   // candidate j -> absolute bucket index
    __shared__ float2   s_c[8][2][KNN];      // compacted {wn, bitcast(id)}
    __shared__ int      s_fn[8][2];

    int lane = threadIdx.x & 31;
    int warp = threadIdx.x >> 5;
    int h = lane >> 4;          // half index: 0 or 1
    int hl = lane & 15;         // lane within half
    int p = blockIdx.x * 16 + warp * 2 + h;
    int pi = p >> 7, pj = p & 127;
    float px = pj + 0.5f, py = pi + 0.5f;
    unsigned lm16 = (1u << hl) - 1u;

    // each lane owns cells 2*hl and 2*hl+1 of the 5x5 neighborhood
    int cA = 2 * hl, cB = 2 * hl + 1;
    int rA = cA / 5, qA = cA - 5 * rA;
    int rB = cB / 5, qB = cB - 5 * rB;
    int cvA = pi - 2 + rA, cuA = pj - 2 + qA;
    int cvB = pi - 2 + rB, cuB = pj - 2 + qB;
    bool okA = (cA < 25) && (cvA >= 0) && (cvA < HH) && (cuA >= 0) && (cuA < WW);
    bool okB = (cB < 25) && (cvB >= 0) && (cvB < HH) && (cuB >= 0) && (cuB < WW);
    int cellA = okA ? (cvA * WW + cuA) : 0;
    int cellB = okB ? (cvB * WW + cuB) : 0;
    int cntA = okA ? min(g_cnt[cellA], CAP) : 0;
    int cntB = okB ? min(g_cnt[cellB], CAP) : 0;

    // width-16 inclusive scan of per-lane pair counts
    int pair = cntA + cntB;
    int incl = pair;
#pragma unroll
    for (int o = 1; o < 16; o <<= 1) {
        int v = __shfl_up_sync(FULLMASK, incl, o, 16);
        if (hl >= o) incl += v;
    }
    int T = __shfl_sync(FULLMASK, incl, 15, 16);
    int exclA = incl - pair;
    int exclB = exclA + cntA;
    int novf = g_cnt[NPIX];

    // warp-uniform fastpath: both halves must qualify
    int To = __shfl_xor_sync(FULLMASK, T, 16);
    bool fastpath = (max(T, To) <= TMAX) && (novf == 0);

    float dsum = 0.0f, c0s = 0.0f, c1s = 0.0f, c2s = 0.0f;
    int anyok = 0;

    if (fastpath) {
        // build absolute-index map (avg ~1.5 stores/lane)
        for (int i = 0; i < cntA; ++i) s_map[warp][h][exclA + i] = cellA * CAP + i;
        for (int i = 0; i < cntB; ++i) s_map[warp][h][exclB + i] = cellB * CAP + i;
        __syncwarp();

        // 3 fixed batches of 16 candidates (no shuffles needed)
        float d2v[3], zv[3];
        int idv[3];
        bool act[3];
#pragma unroll
        for (int b = 0; b < 3; ++b) {
            d2v[b] = 4.0f; zv[b] = 0.0f; idv[b] = 0; act[b] = false;
            int j = b * 16 + hl;
            if (j < T) {
                float4 rec = g_bucket[s_map[warp][h][j]];
                float du = __fsub_rn(px, rec.x);
                float dv = __fsub_rn(py, rec.y);
                float d2 = __fadd_rn(__fmul_rn(du, du), __fmul_rn(dv, dv));
                if (d2 < 4.0f) { act[b] = true; d2v[b] = d2; zv[b] = rec.z; idv[b] = __float_as_int(rec.w); }
            }
        }

        // exact top-16 eviction; loop runs while ANY half needs it (convergent)
        unsigned b0 = (__ballot_sync(FULLMASK, act[0]) >> (h * 16)) & 0xFFFFu;
        unsigned b1 = (__ballot_sync(FULLMASK, act[1]) >> (h * 16)) & 0xFFFFu;
        unsigned b2 = (__ballot_sync(FULLMASK, act[2]) >> (h * 16)) & 0xFFFFu;
        int m = __popc(b0) + __popc(b1) + __popc(b2);
        int mm = max(m, __shfl_xor_sync(FULLMASK, m, 16));
        while (mm > KNN) {
            bool evict = (m > KNN);
            float lmx = -1.0f;
#pragma unroll
            for (int b = 0; b < 3; ++b)
                if (act[b] && d2v[b] > lmx) lmx = d2v[b];
            float gm = lmx;
#pragma unroll
            for (int o = 8; o; o >>= 1)
                gm = fmaxf(gm, __shfl_xor_sync(FULLMASK, gm, o));
            unsigned v2 = (__ballot_sync(FULLMASK, evict && act[2] && d2v[2] == gm) >> (h * 16)) & 0xFFFFu;
            unsigned v1 = (__ballot_sync(FULLMASK, evict && act[1] && d2v[1] == gm) >> (h * 16)) & 0xFFFFu;
            unsigned v0 = (__ballot_sync(FULLMASK, evict && act[0] && d2v[0] == gm) >> (h * 16)) & 0xFFFFu;
            if (v2)      { if (hl == 31 - __clz(v2)) act[2] = false; }
            else if (v1) { if (hl == 31 - __clz(v1)) act[1] = false; }
            else if (v0) { if (hl == 31 - __clz(v0)) act[0] = false; }
            if (evict) --m;
            mm = max(m, __shfl_xor_sync(FULLMASK, m, 16));
        }

        // weights + blend (width-16 reductions: 5 values x 4 steps)
        float w[3];
        float ws = 0.0f, wz = 0.0f, wc0 = 0.0f, wc1 = 0.0f, wc2 = 0.0f;
#pragma unroll
        for (int b = 0; b < 3; ++b) {
            w[b] = act[b] ? __expf(-d2v[b]) : 0.0f;
            ws += w[b];
            wz += w[b] * zv[b];
            if (act[b]) {
                wc0 += w[b] * __ldg(&colors[3 * idv[b] + 0]);
                wc1 += w[b] * __ldg(&colors[3 * idv[b] + 1]);
                wc2 += w[b] * __ldg(&colors[3 * idv[b] + 2]);
            }
        }
#pragma unroll
        for (int o = 8; o; o >>= 1) {
            ws  += __shfl_xor_sync(FULLMASK, ws, o);
            wz  += __shfl_xor_sync(FULLMASK, wz, o);
            wc0 += __shfl_xor_sync(FULLMASK, wc0, o);
            wc1 += __shfl_xor_sync(FULLMASK, wc1, o);
            wc2 += __shfl_xor_sync(FULLMASK, wc2, o);
        }
        float winv = 1.0f / (ws + 1e-10f);
        dsum = wz * winv;
        c0s = wc0 * winv; c1s = wc1 * winv; c2s = wc2 * winv;

        // compact into smem (ranks from post-eviction ballots)
        unsigned e0 = (__ballot_sync(FULLMASK, act[0]) >> (h * 16)) & 0xFFFFu;
        unsigned e1 = (__ballot_sync(FULLMASK, act[1]) >> (h * 16)) & 0xFFFFu;
        unsigned e2 = (__ballot_sync(FULLMASK, act[2]) >> (h * 16)) & 0xFFFFu;
        int n0 = __popc(e0), n1 = __popc(e1);
        if (act[0]) s_c[warp][h][__popc(e0 & lm16)] = make_float2(w[0] * winv, __int_as_float(idv[0]));
        if (act[1]) s_c[warp][h][n0 + __popc(e1 & lm16)] = make_float2(w[1] * winv, __int_as_float(idv[1]));
        if (act[2]) s_c[warp][h][n0 + n1 + __popc(e2 & lm16)] = make_float2(w[2] * winv, __int_as_float(idv[2]));
        if (hl == 0) s_fn[warp][h] = n0 + n1 + __popc(e2);
        anyok = (e0 | e1 | e2) ? 1 : 0;

        if (hl == 0) {
            out[OFF_DEPTH + p] = dsum;
            out[OFF_COLOR + 3 * p + 0] = c0s;
            out[OFF_COLOR + 3 * p + 1] = c1s;
            out[OFF_COLOR + 3 * p + 2] = c2s;
            out[OFF_MASK + p] = anyok ? 1.0f : 0.0f;
        }
    } else {
        // exact scalar fallback: lane 0 of each half handles its pixel
        if (hl == 0) {
            float d2s[KNN], zs[KNN];
            int ids[KNN];
            int n = 0;
            float curmax = -1.0f;
            int argmax = 0;
            int cv0 = max(pi - 2, 0), cv1 = min(pi + 2, HH - 1);
            int cu0 = max(pj - 2, 0), cu1 = min(pj + 2, WW - 1);
            int no = min(novf, OVFCAP);
            for (int a = cv0; a <= cv1 + 1; ++a) {
                bool op = (a == cv1 + 1);
                int blo = op ? 0 : cu0, bhi = op ? 0 : cu1;
                for (int b = blo; b <= bhi; ++b) {
                    int cc;
                    const float4* bk;
                    if (op) { cc = no; bk = g_ovf; }
                    else { int ce = a * WW + b; cc = min(g_cnt[ce], CAP); bk = &g_bucket[ce * CAP]; }
                    for (int s = 0; s < cc; ++s) {
                        float4 rec = bk[s];
                        float du = __fsub_rn(px, rec.x);
                        float dv = __fsub_rn(py, rec.y);
                        float d2 = __fadd_rn(__fmul_rn(du, du), __fmul_rn(dv, dv));
                        if (d2 >= 4.0f) continue;
                        if (n < KNN) {
                            d2s[n] = d2; zs[n] = rec.z; ids[n] = __float_as_int(rec.w);
                            if (d2 > curmax) { curmax = d2; argmax = n; }
                            ++n;
                        } else if (d2 < curmax) {
                            d2s[argmax] = d2; zs[argmax] = rec.z; ids[argmax] = __float_as_int(rec.w);
                            curmax = -1.0f;
                            for (int k = 0; k < KNN; ++k)
                                if (d2s[k] > curmax) { curmax = d2s[k]; argmax = k; }
                        }
                    }
                }
            }
            float ws = 0.0f;
            for (int k = 0; k < n; ++k) { d2s[k] = __expf(-d2s[k]); ws += d2s[k]; }
            float winv = 1.0f / (ws + 1e-10f);
            float ds = 0.0f, a0 = 0.0f, a1 = 0.0f, a2 = 0.0f;
            for (int k = 0; k < n; ++k) {
                float wn = d2s[k] * winv;
                int oi = ids[k];
                ds += zs[k] * wn;
                a0 += __ldg(&colors[3 * oi + 0]) * wn;
                a1 += __ldg(&colors[3 * oi + 1]) * wn;
                a2 += __ldg(&colors[3 * oi + 2]) * wn;
                s_c[warp][h][k] = make_float2(wn, __int_as_float(oi));
            }
            s_fn[warp][h] = n;
            out[OFF_DEPTH + p] = ds;
            out[OFF_COLOR + 3 * p + 0] = a0;
            out[OFF_COLOR + 3 * p + 1] = a1;
            out[OFF_COLOR + 3 * p + 2] = a2;
            out[OFF_MASK + p] = (n > 0) ? 1.0f : 0.0f;
        }
    }
    __syncwarp();

    // zero-pad compacted list to exactly KNN entries
    int n = s_fn[warp][h];
    if (hl >= n) s_c[warp][h][hl] = make_float2(0.0f, __int_as_float(0));
    __syncwarp();

    // ---- feature gather: 16 fixed trips, lane hl covers dims 4*hl..4*hl+3 ----
    const float4* feats4 = (const float4*)feats;
    float ax = 0.0f, ay = 0.0f, az = 0.0f, aw = 0.0f;
#pragma unroll 8
    for (int k = 0; k < KNN; ++k) {
        float2 c = s_c[warp][h][k];              // LDS.64 (2-addr broadcast)
        int id = __float_as_int(c.y);
        float4 f = __ldg(&feats4[id * 16 + hl]); // LDG.128
        ax += c.x * f.x; ay += c.x * f.y; az += c.x * f.z; aw += c.x * f.w;
    }
    float4* outf4 = (float4*)(out + OFF_FEAT);
    outf4[(size_t)p * 16 + hl] = make_float4(ax, ay, az, aw);
}

extern "C" void kernel_launch(void* const* d_in, const int* in_sizes, int n_in,
                              void* d_out, int out_size) {
    const float* pts    = (const float*)d_in[0];
    const float* colors = (const float*)d_in[1];
    const float* feats  = (const float*)d_in[2];
    const float* intr   = (const float*)d_in[3];
    float* out = (float*)d_out;

    void* p_cnt = nullptr;
    cudaGetSymbolAddress(&p_cnt, g_cnt);
    cudaMemsetAsync(p_cnt, 0, sizeof(int) * (NPIX + 1), 0);

    project_bin_kernel<<<NPTS / 256, 256>>>(pts, intr);
    knn_feat_kernel<<<NPIX / 16, 256>>>(colors, feats, out);
}